// round 16
// baseline (speedup 1.0000x reference)
#include <cuda_runtime.h>
#include <cstdint>

#define FAR_DELTA 1e10f

// R7/R15 policy mix (verified twice: 22.5us):
//   density + depth -> __ldg, feature -> __ldcs
// New this round: 2 rays per warp. All 10 LDG.128s front-batched (2x in-flight
// bytes per warp) and the two rays' serial shfl scan/reduce chains run with
// ILP-2, covering the warm-L2-state latency that neither DRAM nor LTS
// saturation explains (22.5us vs ~16us leg bound).

__global__ void volrend_kernel(const float* __restrict__ density,
                               const float* __restrict__ depth,
                               const float* __restrict__ feature,
                               float* __restrict__ out,
                               int numRays)
{
    const unsigned FULL = 0xffffffffu;
    const int lane = threadIdx.x & 31;
    const int w    = (int)((blockIdx.x * (unsigned)blockDim.x + threadIdx.x) >> 5);
    int r0 = 2 * w;
    if (r0 >= numRays) return;
    int r1 = r0 + 1;
    const bool have1 = (r1 < numRays);
    const int r1c = have1 ? r1 : r0;     // clamp: duplicate loads, store guarded

    const unsigned dzOff0 = (unsigned)r0  * 128u + 4u * lane;
    const unsigned dzOff1 = (unsigned)r1c * 128u + 4u * lane;
    const unsigned fOff0  = (unsigned)r0  * 384u + 12u * lane;
    const unsigned fOff1  = (unsigned)r1c * 384u + 12u * lane;

    // ---- 10 front-batched loads (policy per R7) ----
    const float4 dA = __ldg(reinterpret_cast<const float4*>(density + dzOff0));
    const float4 zA = __ldg(reinterpret_cast<const float4*>(depth + dzOff0));
    const float4 dB = __ldg(reinterpret_cast<const float4*>(density + dzOff1));
    const float4 zB = __ldg(reinterpret_cast<const float4*>(depth + dzOff1));
    const float4* fpA = reinterpret_cast<const float4*>(feature + fOff0);
    const float4* fpB = reinterpret_cast<const float4*>(feature + fOff1);
    const float4 fA0 = __ldcs(fpA + 0);
    const float4 fA1 = __ldcs(fpA + 1);
    const float4 fA2 = __ldcs(fpA + 2);
    const float4 fB0 = __ldcs(fpB + 0);
    const float4 fB1 = __ldcs(fpB + 1);
    const float4 fB2 = __ldcs(fpB + 2);

    // ---- deltas (both rays) ----
    float znA = __shfl_down_sync(FULL, zA.x, 1);
    float znB = __shfl_down_sync(FULL, zB.x, 1);
    float a0 = zA.y - zA.x, a1 = zA.z - zA.y, a2 = zA.w - zA.z;
    float a3 = (lane == 31) ? FAR_DELTA : (znA - zA.w);
    float b0 = zB.y - zB.x, b1 = zB.z - zB.y, b2 = zB.w - zB.z;
    float b3 = (lane == 31) ? FAR_DELTA : (znB - zB.w);

    // ---- segment transmittances (both rays) ----
    float sA0 = __expf(-dA.x * a0), sA1 = __expf(-dA.y * a1);
    float sA2 = __expf(-dA.z * a2), sA3 = __expf(-dA.w * a3);
    float sB0 = __expf(-dB.x * b0), sB1 = __expf(-dB.y * b1);
    float sB2 = __expf(-dB.z * b2), sB3 = __expf(-dB.w * b3);

    // ---- interleaved multiplicative warp scans (ILP-2 on the shfl chain) ----
    float PA = sA0 * sA1 * sA2 * sA3;
    float PB = sB0 * sB1 * sB2 * sB3;
    #pragma unroll
    for (int off = 1; off < 32; off <<= 1) {
        float vA = __shfl_up_sync(FULL, PA, off);
        float vB = __shfl_up_sync(FULL, PB, off);
        if (lane >= off) { PA *= vA; PB *= vB; }
    }
    float TA = __shfl_up_sync(FULL, PA, 1);
    float TB = __shfl_up_sync(FULL, PB, 1);
    if (lane == 0) { TA = 1.0f; TB = 1.0f; }

    // ---- weights + fused accumulation (both rays) ----
    float wA0 = TA * (1.0f - sA0); TA *= sA0;
    float wA1 = TA * (1.0f - sA1); TA *= sA1;
    float wA2 = TA * (1.0f - sA2); TA *= sA2;
    float wA3 = TA * (1.0f - sA3);
    float wB0 = TB * (1.0f - sB0); TB *= sB0;
    float wB1 = TB * (1.0f - sB1); TB *= sB1;
    float wB2 = TB * (1.0f - sB2); TB *= sB2;
    float wB3 = TB * (1.0f - sB3);

    // feature layout per lane: s0:(f0.x f0.y f0.z) s1:(f0.w f1.x f1.y)
    //                          s2:(f1.z f1.w f2.x) s3:(f2.y f2.z f2.w)
    float axA = wA0*fA0.x + wA1*fA0.w + wA2*fA1.z + wA3*fA2.y;
    float ayA = wA0*fA0.y + wA1*fA1.x + wA2*fA1.w + wA3*fA2.z;
    float azA = wA0*fA0.z + wA1*fA1.y + wA2*fA2.x + wA3*fA2.w;
    float adA = wA0*zA.x  + wA1*zA.y  + wA2*zA.z  + wA3*zA.w;
    float axB = wB0*fB0.x + wB1*fB0.w + wB2*fB1.z + wB3*fB2.y;
    float ayB = wB0*fB0.y + wB1*fB1.x + wB2*fB1.w + wB3*fB2.z;
    float azB = wB0*fB0.z + wB1*fB1.y + wB2*fB2.x + wB3*fB2.w;
    float adB = wB0*zB.x  + wB1*zB.y  + wB2*zB.z  + wB3*zB.w;

    // ---- interleaved butterfly reductions (ILP-8) ----
    #pragma unroll
    for (int off = 16; off >= 1; off >>= 1) {
        axA += __shfl_xor_sync(FULL, axA, off);
        ayA += __shfl_xor_sync(FULL, ayA, off);
        azA += __shfl_xor_sync(FULL, azA, off);
        adA += __shfl_xor_sync(FULL, adA, off);
        axB += __shfl_xor_sync(FULL, axB, off);
        ayB += __shfl_xor_sync(FULL, ayB, off);
        azB += __shfl_xor_sync(FULL, azB, off);
        adB += __shfl_xor_sync(FULL, adB, off);
    }

    if (lane == 0) {
        out[(unsigned)r0 * 3 + 0] = axA;
        out[(unsigned)r0 * 3 + 1] = ayA;
        out[(unsigned)r0 * 3 + 2] = azA;
        out[(unsigned)numRays * 3 + (unsigned)r0] = adA;
        if (have1) {
            out[(unsigned)r1 * 3 + 0] = axB;
            out[(unsigned)r1 * 3 + 1] = ayB;
            out[(unsigned)r1 * 3 + 2] = azB;
            out[(unsigned)numRays * 3 + (unsigned)r1] = adB;
        }
    }
}

extern "C" void kernel_launch(void* const* d_in, const int* in_sizes, int n_in,
                              void* d_out, int out_size)
{
    const float* density = (const float*)d_in[0];
    const float* depth   = (const float*)d_in[1];
    const float* feature = (const float*)d_in[2];
    float* out = (float*)d_out;

    int numRays = in_sizes[0] / 128;            // density is [N,128]
    int numWarps = (numRays + 1) / 2;           // 2 rays per warp
    int warpsPerBlock = 256 / 32;
    int blocks = (numWarps + warpsPerBlock - 1) / warpsPerBlock;

    volrend_kernel<<<blocks, 256>>>(density, depth, feature, out, numRays);
}

// round 17
// speedup vs baseline: 1.0907x; 1.0907x over previous
#include <cuda_runtime.h>
#include <cstdint>

#define FAR_DELTA 1e10f

// R7/R15 policy mix (verified: 22.5us): density+depth -> __ldg, feature -> __ldcs.
// New: persistent single-wave launch (1184 blocks = 148 SMs x 8 resident at
// 32 regs). In the WARM L2 regime the kernel is overhead-dominated (22.5us vs
// ~16us leg bound); the ~7 wave transitions of the 8192-block launch are the
// prime suspect. (Persistent was only ever tested cold, where DRAM saturation
// hid wave gaps.) Per-ray body identical to R15.

__global__ __launch_bounds__(256, 8)
void volrend_kernel(const float* __restrict__ density,
                    const float* __restrict__ depth,
                    const float* __restrict__ feature,
                    float* __restrict__ out,
                    int numRays)
{
    const unsigned FULL = 0xffffffffu;
    const int lane = threadIdx.x & 31;
    const int warpGlobal = (int)((blockIdx.x * (unsigned)blockDim.x + threadIdx.x) >> 5);
    const int totalWarps = (int)(gridDim.x * (blockDim.x >> 5));

    for (int ray = warpGlobal; ray < numRays; ray += totalWarps) {
        const unsigned dzOff = (unsigned)ray * 128u + 4u * lane;
        const unsigned fOff  = (unsigned)ray * 384u + 12u * lane;

        // ---- density/depth: normal-priority cached (resident across replays) ----
        const float4 d4 = __ldg(reinterpret_cast<const float4*>(density + dzOff));
        const float4 z4 = __ldg(reinterpret_cast<const float4*>(depth + dzOff));

        // ---- feature: streaming (evict-first) ----
        const float4* fptr = reinterpret_cast<const float4*>(feature + fOff);
        const float4 f0 = __ldcs(fptr + 0);
        const float4 f1 = __ldcs(fptr + 1);
        const float4 f2 = __ldcs(fptr + 2);

        // ---- deltas ----
        float znext = __shfl_down_sync(FULL, z4.x, 1);
        float del0 = z4.y - z4.x;
        float del1 = z4.z - z4.y;
        float del2 = z4.w - z4.z;
        float del3 = (lane == 31) ? FAR_DELTA : (znext - z4.w);

        // ---- segment transmittances ----
        float s0 = __expf(-d4.x * del0);
        float s1 = __expf(-d4.y * del1);
        float s2 = __expf(-d4.z * del2);
        float s3 = __expf(-d4.w * del3);

        // ---- multiplicative warp scan -> exclusive T ----
        float P = s0 * s1 * s2 * s3;
        #pragma unroll
        for (int off = 1; off < 32; off <<= 1) {
            float v = __shfl_up_sync(FULL, P, off);
            if (lane >= off) P *= v;
        }
        float T = __shfl_up_sync(FULL, P, 1);
        if (lane == 0) T = 1.0f;

        // ---- weights + fused accumulation ----
        float w0 = T * (1.0f - s0); T *= s0;
        float w1 = T * (1.0f - s1); T *= s1;
        float w2 = T * (1.0f - s2); T *= s2;
        float w3 = T * (1.0f - s3);

        // feature layout per lane: s0:(f0.x f0.y f0.z) s1:(f0.w f1.x f1.y)
        //                          s2:(f1.z f1.w f2.x) s3:(f2.y f2.z f2.w)
        float ax = w0 * f0.x + w1 * f0.w + w2 * f1.z + w3 * f2.y;
        float ay = w0 * f0.y + w1 * f1.x + w2 * f1.w + w3 * f2.z;
        float az = w0 * f0.z + w1 * f1.y + w2 * f2.x + w3 * f2.w;
        float ad = w0 * z4.x + w1 * z4.y + w2 * z4.z + w3 * z4.w;

        // ---- warp butterfly reduction ----
        #pragma unroll
        for (int off = 16; off >= 1; off >>= 1) {
            ax += __shfl_xor_sync(FULL, ax, off);
            ay += __shfl_xor_sync(FULL, ay, off);
            az += __shfl_xor_sync(FULL, az, off);
            ad += __shfl_xor_sync(FULL, ad, off);
        }

        if (lane == 0) {
            out[(unsigned)ray * 3 + 0] = ax;                    // feature [N,3]
            out[(unsigned)ray * 3 + 1] = ay;
            out[(unsigned)ray * 3 + 2] = az;
            out[(unsigned)numRays * 3 + (unsigned)ray] = ad;    // depth [N,1]
        }
    }
}

extern "C" void kernel_launch(void* const* d_in, const int* in_sizes, int n_in,
                              void* d_out, int out_size)
{
    const float* density = (const float*)d_in[0];
    const float* depth   = (const float*)d_in[1];
    const float* feature = (const float*)d_in[2];
    float* out = (float*)d_out;

    int numRays = in_sizes[0] / 128;   // density is [N,128]

    // Single-wave persistent: 148 SMs x 8 blocks x 256 thr (32 regs forced)
    int blocks = 1184;
    int maxBlocks = (numRays * 32 + 255) / 256;
    if (blocks > maxBlocks) blocks = maxBlocks;

    volrend_kernel<<<blocks, 256>>>(density, depth, feature, out, numRays);
}